// round 8
// baseline (speedup 1.0000x reference)
#include <cuda_runtime.h>

// Per-edge dot product: out[e] = dot(h[src[e]], h[dst[e]]), D=64 fp32.
// Indices arrive as int32 (JAX x64 disabled).
//
// R7: L2 at 67.5%, occ 61.8%, issue 29.7% -> still latency-exposed. Raise
// aggregate outstanding gathers: THREE edges per 8-lane group = 12 independent
// LDG.E.128 per thread issued back-to-back before any FMA. ~64 regs -> ~50%
// occupancy, but outstanding loads/SMSP rises ~80 -> ~96, pushing L2 toward
// saturation (~22us projected wall).
__global__ void __launch_bounds__(256) edge_dot_kernel(
    const float4* __restrict__ h,     // [N, 16] as float4 (D=64)
    const int* __restrict__ src,      // [E] int32
    const int* __restrict__ dst,      // [E] int32
    float* __restrict__ out,          // [E]
    int E)
{
    int tid   = blockIdx.x * blockDim.x + threadIdx.x;
    int group = tid >> 3;             // 8 lanes per group, 3 edges per group
    int lane  = tid & 7;

    int e0 = group * 3;
    if (e0 >= E) return;
    int e1 = e0 + 1;
    int e2 = e0 + 2;
    bool has1 = (e1 < E);
    bool has2 = (e2 < E);

    // Hoist all index loads (warp-broadcast, L1-resident)
    int s0 = __ldg(src + e0);
    int d0 = __ldg(dst + e0);
    int s1 = has1 ? __ldg(src + e1) : s0;
    int d1 = has1 ? __ldg(dst + e1) : d0;
    int s2 = has2 ? __ldg(src + e2) : s0;
    int d2 = has2 ? __ldg(dst + e2) : d0;

    const float4* __restrict__ hu0 = h + (long long)s0 * 16;
    const float4* __restrict__ hv0 = h + (long long)d0 * 16;
    const float4* __restrict__ hu1 = h + (long long)s1 * 16;
    const float4* __restrict__ hv1 = h + (long long)d1 * 16;
    const float4* __restrict__ hu2 = h + (long long)s2 * 16;
    const float4* __restrict__ hv2 = h + (long long)d2 * 16;

    // 12 independent 16B loads -> deep MLP. Each 256B row is covered by the
    // 8-lane group as two fully-coalesced 128B lines.
    float4 a00 = hu0[lane];
    float4 a01 = hu0[lane + 8];
    float4 b00 = hv0[lane];
    float4 b01 = hv0[lane + 8];
    float4 a10 = hu1[lane];
    float4 a11 = hu1[lane + 8];
    float4 b10 = hv1[lane];
    float4 b11 = hv1[lane + 8];
    float4 a20 = hu2[lane];
    float4 a21 = hu2[lane + 8];
    float4 b20 = hv2[lane];
    float4 b21 = hv2[lane + 8];

    float p0 = a00.x * b00.x + a00.y * b00.y + a00.z * b00.z + a00.w * b00.w
             + a01.x * b01.x + a01.y * b01.y + a01.z * b01.z + a01.w * b01.w;
    float p1 = a10.x * b10.x + a10.y * b10.y + a10.z * b10.z + a10.w * b10.w
             + a11.x * b11.x + a11.y * b11.y + a11.z * b11.z + a11.w * b11.w;
    float p2 = a20.x * b20.x + a20.y * b20.y + a20.z * b20.z + a20.w * b20.w
             + a21.x * b21.x + a21.y * b21.y + a21.z * b21.z + a21.w * b21.w;

    // Butterfly reduce all three edges across the 8-lane group
    p0 += __shfl_xor_sync(0xFFFFFFFFu, p0, 4);
    p1 += __shfl_xor_sync(0xFFFFFFFFu, p1, 4);
    p2 += __shfl_xor_sync(0xFFFFFFFFu, p2, 4);
    p0 += __shfl_xor_sync(0xFFFFFFFFu, p0, 2);
    p1 += __shfl_xor_sync(0xFFFFFFFFu, p1, 2);
    p2 += __shfl_xor_sync(0xFFFFFFFFu, p2, 2);
    p0 += __shfl_xor_sync(0xFFFFFFFFu, p0, 1);
    p1 += __shfl_xor_sync(0xFFFFFFFFu, p1, 1);
    p2 += __shfl_xor_sync(0xFFFFFFFFu, p2, 1);

    if (lane == 0) {
        out[e0] = p0;
        if (has1) out[e1] = p1;
        if (has2) out[e2] = p2;
    }
}

extern "C" void kernel_launch(void* const* d_in, const int* in_sizes, int n_in,
                              void* d_out, int out_size)
{
    const float4* h   = (const float4*)d_in[0];
    const int*    src = (const int*)d_in[1];
    const int*    dst = (const int*)d_in[2];
    float*        out = (float*)d_out;

    int E = in_sizes[1];

    int threads = 256;
    long long groups = ((long long)E + 2) / 3;      // 3 edges per group
    long long total  = groups * 8;                  // 8 lanes per group
    int blocks = (int)((total + threads - 1) / threads);
    edge_dot_kernel<<<blocks, threads>>>(h, src, dst, out, E);
}